// round 1
// baseline (speedup 1.0000x reference)
#include <cuda_runtime.h>

#define LN 2
#define NR 768
#define NA 14

// output layout: fape_loss[2], rotamer_loss[2], final_ae[768*768], rotamer_error[-1][768], lddt[768]
#define OFF_AE   4
#define OFF_RE   (4 + NR * NR)
#define OFF_LDDT (OFF_RE + NR)

// ---- device scratch (no allocations allowed) ----
__device__ float g_Qo[LN * NR * 12];    // per (l,i): Q row-major [9], o [3]
__device__ float g_fape[LN * NR * NR];  // fape[l,i,j]
__device__ int   g_bits[NR];            // atom-mask bitmask per residue
__device__ float g_row[NR * 8];         // per-row partials: s0,s1,o0,o1,cs,co,diag0,diag1

__device__ __forceinline__ float sqrt_approx(float x) {
    float r; asm("sqrt.approx.f32 %0, %1;" : "=f"(r) : "f"(x)); return r;
}
__device__ __forceinline__ float rsqrt_approx(float x) {
    float r; asm("rsqrt.approx.f32 %0, %1;" : "=f"(r) : "f"(x)); return r;
}

__device__ __forceinline__ void make_frame(const float n[3], const float ca[3], const float c[3],
                                           float e1[3], float e2[3], float e3[3]) {
    // e1 = normalize(c - ca)
    e1[0] = c[0] - ca[0]; e1[1] = c[1] - ca[1]; e1[2] = c[2] - ca[2];
    float s1 = e1[0]*e1[0] + e1[1]*e1[1] + e1[2]*e1[2];
    float i1 = rsqrt_approx(fmaxf(s1, 1e-6f));
    e1[0] *= i1; e1[1] *= i1; e1[2] *= i1;
    // e2 = normalize((n-ca) - dot(e1, n-ca)*e1)
    float v2[3] = { n[0]-ca[0], n[1]-ca[1], n[2]-ca[2] };
    float dt = e1[0]*v2[0] + e1[1]*v2[1] + e1[2]*v2[2];
    e2[0] = v2[0] - dt*e1[0]; e2[1] = v2[1] - dt*e1[1]; e2[2] = v2[2] - dt*e1[2];
    float s2 = e2[0]*e2[0] + e2[1]*e2[1] + e2[2]*e2[2];
    float i2 = rsqrt_approx(fmaxf(s2, 1e-6f));
    e2[0] *= i2; e2[1] *= i2; e2[2] *= i2;
    // e3 = cross(e1, e2)
    e3[0] = e1[1]*e2[2] - e1[2]*e2[1];
    e3[1] = e1[2]*e2[0] - e1[0]*e2[2];
    e3[2] = e1[0]*e2[1] - e1[1]*e2[0];
}

// ---- kernel 1: frames + Q = Rp Rg^T, o = tp - Q tg, atom bitmasks ----
__global__ void frames_kernel(const float* __restrict__ pred, const float* __restrict__ gt,
                              const float* __restrict__ am) {
    int i = blockIdx.x * blockDim.x + threadIdx.x;
    if (i >= NR) return;

    int bits = 0;
#pragma unroll
    for (int a = 0; a < NA; a++)
        if (am[i * NA + a] > 0.f) bits |= (1 << a);
    g_bits[i] = bits;

    const float* gb = gt + i * NA * 3;
    float gn[3]  = { gb[0], gb[1], gb[2] };
    float gca[3] = { gb[3], gb[4], gb[5] };
    float gc[3]  = { gb[6], gb[7], gb[8] };
    float e1g[3], e2g[3], e3g[3];
    make_frame(gn, gca, gc, e1g, e2g, e3g);

#pragma unroll
    for (int l = 0; l < LN; l++) {
        const float* pb = pred + (size_t)(l * NR + i) * NA * 3;
        float pn[3]  = { pb[0], pb[1], pb[2] };
        float pca[3] = { pb[3], pb[4], pb[5] };
        float pc[3]  = { pb[6], pb[7], pb[8] };
        float e1p[3], e2p[3], e3p[3];
        make_frame(pn, pca, pc, e1p, e2p, e3p);

        float* dst = g_Qo + (size_t)(l * NR + i) * 12;
#pragma unroll
        for (int d = 0; d < 3; d++) {
            float q0 = e1p[d]*e1g[0] + e2p[d]*e2g[0] + e3p[d]*e3g[0];
            float q1 = e1p[d]*e1g[1] + e2p[d]*e2g[1] + e3p[d]*e3g[1];
            float q2 = e1p[d]*e1g[2] + e2p[d]*e2g[2] + e3p[d]*e3g[2];
            dst[3*d+0] = q0; dst[3*d+1] = q1; dst[3*d+2] = q2;
            dst[9 + d] = pca[d] - (q0*gca[0] + q1*gca[1] + q2*gca[2]);
        }
    }
}

// ---- kernel 2: main FAPE over (l, i, j) with 14-atom inner loop ----
__global__ __launch_bounds__(256) void fape_kernel(const float* __restrict__ pred,
                                                   const float* __restrict__ gt,
                                                   const int* __restrict__ batch,
                                                   float* __restrict__ out_ae) {
    __shared__ float4 sP[16 * 15];   // pred points for j-tile (padded stride 15)
    __shared__ float4 sG[16 * 15];   // gt points for j-tile
    __shared__ float  sQ[16 * 12];   // Q+o for i-tile
    __shared__ int    sBatI[16], sBatJ[16], sBitI[16], sBitJ[16];

    const int l  = blockIdx.z;
    const int i0 = blockIdx.y * 16, j0 = blockIdx.x * 16;
    const int tid = threadIdx.y * 16 + threadIdx.x;

    // stage point tiles (224 float4 entries each)
    if (tid < 16 * NA) {
        int j = tid / NA, a = tid % NA;
        const float* pp = pred + ((size_t)(l * NR + j0 + j) * NA + a) * 3;
        sP[j * 15 + a] = make_float4(pp[0], pp[1], pp[2], 0.f);
        const float* gp = gt + ((size_t)(j0 + j) * NA + a) * 3;
        sG[j * 15 + a] = make_float4(gp[0], gp[1], gp[2], 0.f);
    }
    if (tid < 192) sQ[tid] = g_Qo[(size_t)(l * NR + i0) * 12 + tid];
    if (tid < 16)        { sBatI[tid] = batch[i0 + tid]; sBitI[tid] = g_bits[i0 + tid]; }
    else if (tid < 32)   { int t = tid - 16; sBatJ[t] = batch[j0 + t]; sBitJ[t] = g_bits[j0 + t]; }
    __syncthreads();

    const int ti = threadIdx.y, tj = threadIdx.x;
    float fape = 0.f;
    if (sBatI[ti] == sBatJ[tj]) {
        const unsigned mb = (unsigned)(sBitI[ti] & sBitJ[tj]);
        float q[12];
#pragma unroll
        for (int k = 0; k < 12; k++) q[k] = sQ[ti * 12 + k];
        float se = 0.f;
#pragma unroll
        for (int a = 0; a < NA; a++) {
            float4 g = sG[tj * 15 + a];
            float4 p = sP[tj * 15 + a];
            float w0 = fmaf(q[0], g.x, fmaf(q[1], g.y, fmaf(q[2], g.z, q[9])));
            float w1 = fmaf(q[3], g.x, fmaf(q[4], g.y, fmaf(q[5], g.z, q[10])));
            float w2 = fmaf(q[6], g.x, fmaf(q[7], g.y, fmaf(q[8], g.z, q[11])));
            float d0 = p.x - w0, d1 = p.y - w1, d2 = p.z - w2;
            float n2 = fmaf(d0, d0, fmaf(d1, d1, d2 * d2));
            float err = sqrt_approx(fmaxf(n2, 1e-6f));
            se += ((mb >> a) & 1u) ? err : 0.f;
        }
        fape = se / fmaxf((float)__popc(mb), 1e-6f);
    }
    const int i = i0 + ti, j = j0 + tj;
    g_fape[(size_t)(l * NR + i) * NR + j] = fape;
    if (l == 1) out_ae[i * NR + j] = fape;
}

__device__ __forceinline__ float warp_sum(float v) {
#pragma unroll
    for (int o = 16; o > 0; o >>= 1) v += __shfl_down_sync(0xffffffffu, v, o);
    return v;
}

// ---- kernel 3: per-row masked/clipped sums + diag extraction ----
__global__ __launch_bounds__(256) void row_kernel(const int* __restrict__ batch,
                                                  const int* __restrict__ chain,
                                                  float* __restrict__ out) {
    const int i = blockIdx.x;
    const int bi = g_bits[i], bati = batch[i], chi = chain[i];
    float acc[6] = {0.f, 0.f, 0.f, 0.f, 0.f, 0.f}; // same0, same1, other0, other1, cnt_same, cnt_other
    const float* f0 = g_fape + (size_t)i * NR;
    const float* f1 = g_fape + (size_t)(NR + i) * NR;

    for (int j = threadIdx.x; j < NR; j += 256) {
        bool pm2 = (bati == batch[j]) && ((bi & g_bits[j]) != 0);
        if (pm2) {
            float c0 = fminf(f0[j], 10.f);
            float c1 = fminf(f1[j], 10.f);
            if (chi == chain[j]) { acc[0] += c0; acc[1] += c1; acc[4] += 1.f; }
            else                 { acc[2] += c0; acc[3] += c1; acc[5] += 1.f; }
        }
    }
    __shared__ float sred[8][6];
    const int lane = threadIdx.x & 31, wid = threadIdx.x >> 5;
#pragma unroll
    for (int k = 0; k < 6; k++) {
        float v = warp_sum(acc[k]);
        if (lane == 0) sred[wid][k] = v;
    }
    __syncthreads();
    if (threadIdx.x < 6) {
        float v = 0.f;
#pragma unroll
        for (int w = 0; w < 8; w++) v += sred[w][threadIdx.x];
        g_row[i * 8 + threadIdx.x] = v;
    }
    if (threadIdx.x == 6) g_row[i * 8 + 6] = f0[i];
    if (threadIdx.x == 7) {
        float d1 = f1[i];
        g_row[i * 8 + 7] = d1;
        out[OFF_RE + i] = d1;   // rotamer_error[-1]
    }
}

// ---- kernel 4: finalize scalar outputs ----
__global__ __launch_bounds__(256) void final_kernel(float* __restrict__ out) {
    float acc[9] = {0.f,0.f,0.f,0.f,0.f,0.f,0.f,0.f,0.f};
    for (int i = threadIdx.x; i < NR; i += 256) {
#pragma unroll
        for (int k = 0; k < 8; k++) acc[k] += g_row[i * 8 + k];
        acc[8] += (g_bits[i] != 0) ? 1.f : 0.f;
    }
    __shared__ float sred[8][9];
    const int lane = threadIdx.x & 31, wid = threadIdx.x >> 5;
#pragma unroll
    for (int k = 0; k < 9; k++) {
        float v = warp_sum(acc[k]);
        if (lane == 0) sred[wid][k] = v;
    }
    __syncthreads();
    if (threadIdx.x == 0) {
        float tot[9];
#pragma unroll
        for (int k = 0; k < 9; k++) {
            float v = 0.f;
#pragma unroll
            for (int w = 0; w < 8; w++) v += sred[w][k];
            tot[k] = v;
        }
        float invCS = 0.1f / fmaxf(tot[4], 1e-6f);
        float invCO = 0.1f / fmaxf(tot[5], 1e-6f);
        float nres  = fmaxf(tot[8], 1e-6f);
        out[0] = tot[0] * invCS + tot[2] * invCO;  // fape_loss[0]
        out[1] = tot[1] * invCS + tot[3] * invCO;  // fape_loss[1]
        out[2] = tot[6] / nres;                    // rotamer_loss[0]
        out[3] = tot[7] / nres;                    // rotamer_loss[1]
    }
}

// ---- kernel 5: lDDT ----
__global__ __launch_bounds__(256) void lddt_kernel(const float* __restrict__ pred,
                                                   const float* __restrict__ gt,
                                                   float* __restrict__ out) {
    __shared__ float sg[NR][3];
    __shared__ float sp[NR][3];
    __shared__ int   srm[NR];
    for (int j = threadIdx.x; j < NR; j += 256) {
        const float* gp = gt + ((size_t)j * NA + 1) * 3;
        sg[j][0] = gp[0]; sg[j][1] = gp[1]; sg[j][2] = gp[2];
        const float* pp = pred + ((size_t)(1 * NR + j) * NA + 1) * 3;  // pred[-1]
        sp[j][0] = pp[0]; sp[j][1] = pp[1]; sp[j][2] = pp[2];
        srm[j] = (g_bits[j] != 0);
    }
    __syncthreads();

    const int i = blockIdx.x;
    const float gix = sg[i][0], giy = sg[i][1], giz = sg[i][2];
    const float pix = sp[i][0], piy = sp[i][1], piz = sp[i][2];
    float suml = 0.f, cnt = 0.f;
    if (srm[i]) {
        for (int j = threadIdx.x; j < NR; j += 256) {
            if (j == i || !srm[j]) continue;
            float dx = gix - sg[j][0], dy = giy - sg[j][1], dz = giz - sg[j][2];
            float gd = sqrt_approx(fmaxf(dx*dx + dy*dy + dz*dz, 1e-6f));
            if (gd < 15.f) {
                float ex = pix - sp[j][0], ey = piy - sp[j][1], ez = piz - sp[j][2];
                float d = sqrt_approx(fmaxf(ex*ex + ey*ey + ez*ez, 1e-6f));
                float derr = fabsf(gd - d);
                int c = (derr < 0.5f) + (derr < 1.0f) + (derr < 2.0f) + (derr < 4.0f);
                suml += 0.25f * (float)c;
                cnt  += 1.f;
            }
        }
    }
    __shared__ float sred[8][2];
    const int lane = threadIdx.x & 31, wid = threadIdx.x >> 5;
    float v0 = warp_sum(suml), v1 = warp_sum(cnt);
    if (lane == 0) { sred[wid][0] = v0; sred[wid][1] = v1; }
    __syncthreads();
    if (threadIdx.x == 0) {
        float s = 0.f, c = 0.f;
#pragma unroll
        for (int w = 0; w < 8; w++) { s += sred[w][0]; c += sred[w][1]; }
        out[OFF_LDDT + i] = s / fmaxf(c, 1e-6f);
    }
}

extern "C" void kernel_launch(void* const* d_in, const int* in_sizes, int n_in,
                              void* d_out, int out_size) {
    const float* pred  = (const float*)d_in[0];
    const float* gt    = (const float*)d_in[1];
    const float* am    = (const float*)d_in[2];
    const int*   batch = (const int*)d_in[3];
    const int*   chain = (const int*)d_in[4];
    float* out = (float*)d_out;

    frames_kernel<<<(NR + 255) / 256, 256>>>(pred, gt, am);

    dim3 grid(NR / 16, NR / 16, LN), blk(16, 16);
    fape_kernel<<<grid, blk>>>(pred, gt, batch, out + OFF_AE);

    row_kernel<<<NR, 256>>>(batch, chain, out);
    final_kernel<<<1, 256>>>(out);
    lddt_kernel<<<NR, 256>>>(pred, gt, out);
}

// round 2
// speedup vs baseline: 1.7536x; 1.7536x over previous
#include <cuda_runtime.h>

#define LN 2
#define NR 768
#define NA 14
#define TILE 32

// output layout: fape_loss[2], rotamer_loss[2], final_ae[768*768], rotamer_error[-1][768], lddt[768]
#define OFF_AE   4
#define OFF_RE   (4 + NR * NR)
#define OFF_LDDT (OFF_RE + NR)

// ---- device scratch (no allocations allowed) ----
__device__ float g_Qo[LN * NR * 12];    // per (l,i): Q row-major [9], o [3]
__device__ int   g_bits[NR];            // atom-mask bitmask per residue
__device__ float g_acc[8];              // intra0,intra1,inter0,inter1,cnt_s,cnt_o,diag0,diag1

__device__ __forceinline__ float sqrt_approx(float x) {
    float r; asm("sqrt.approx.f32 %0, %1;" : "=f"(r) : "f"(x)); return r;
}
__device__ __forceinline__ float rsqrt_approx(float x) {
    float r; asm("rsqrt.approx.f32 %0, %1;" : "=f"(r) : "f"(x)); return r;
}
__device__ __forceinline__ float warp_sum(float v) {
#pragma unroll
    for (int o = 16; o > 0; o >>= 1) v += __shfl_down_sync(0xffffffffu, v, o);
    return v;
}

__device__ __forceinline__ void make_frame(const float n[3], const float ca[3], const float c[3],
                                           float e1[3], float e2[3], float e3[3]) {
    e1[0] = c[0] - ca[0]; e1[1] = c[1] - ca[1]; e1[2] = c[2] - ca[2];
    float s1 = e1[0]*e1[0] + e1[1]*e1[1] + e1[2]*e1[2];
    float i1 = rsqrt_approx(fmaxf(s1, 1e-6f));
    e1[0] *= i1; e1[1] *= i1; e1[2] *= i1;
    float v2[3] = { n[0]-ca[0], n[1]-ca[1], n[2]-ca[2] };
    float dt = e1[0]*v2[0] + e1[1]*v2[1] + e1[2]*v2[2];
    e2[0] = v2[0] - dt*e1[0]; e2[1] = v2[1] - dt*e1[1]; e2[2] = v2[2] - dt*e1[2];
    float s2 = e2[0]*e2[0] + e2[1]*e2[1] + e2[2]*e2[2];
    float i2 = rsqrt_approx(fmaxf(s2, 1e-6f));
    e2[0] *= i2; e2[1] *= i2; e2[2] *= i2;
    e3[0] = e1[1]*e2[2] - e1[2]*e2[1];
    e3[1] = e1[2]*e2[0] - e1[0]*e2[2];
    e3[2] = e1[0]*e2[1] - e1[1]*e2[0];
}

// ---- kernel 1: frames + Q = Rp Rg^T, o = tp - Q tg, atom bitmasks, zero accumulators ----
__global__ void frames_kernel(const float* __restrict__ pred, const float* __restrict__ gt,
                              const float* __restrict__ am) {
    int i = blockIdx.x * blockDim.x + threadIdx.x;
    if (i < 8) g_acc[i] = 0.f;
    if (i >= NR) return;

    int bits = 0;
#pragma unroll
    for (int a = 0; a < NA; a++)
        if (am[i * NA + a] > 0.f) bits |= (1 << a);
    g_bits[i] = bits;

    const float* gb = gt + i * NA * 3;
    float gn[3]  = { gb[0], gb[1], gb[2] };
    float gca[3] = { gb[3], gb[4], gb[5] };
    float gc[3]  = { gb[6], gb[7], gb[8] };
    float e1g[3], e2g[3], e3g[3];
    make_frame(gn, gca, gc, e1g, e2g, e3g);

#pragma unroll
    for (int l = 0; l < LN; l++) {
        const float* pb = pred + (size_t)(l * NR + i) * NA * 3;
        float pn[3]  = { pb[0], pb[1], pb[2] };
        float pca[3] = { pb[3], pb[4], pb[5] };
        float pc[3]  = { pb[6], pb[7], pb[8] };
        float e1p[3], e2p[3], e3p[3];
        make_frame(pn, pca, pc, e1p, e2p, e3p);

        float* dst = g_Qo + (size_t)(l * NR + i) * 12;
#pragma unroll
        for (int d = 0; d < 3; d++) {
            float q0 = e1p[d]*e1g[0] + e2p[d]*e2g[0] + e3p[d]*e3g[0];
            float q1 = e1p[d]*e1g[1] + e2p[d]*e2g[1] + e3p[d]*e3g[1];
            float q2 = e1p[d]*e1g[2] + e2p[d]*e2g[2] + e3p[d]*e3g[2];
            dst[3*d+0] = q0; dst[3*d+1] = q1; dst[3*d+2] = q2;
            dst[9 + d] = pca[d] - (q0*gca[0] + q1*gca[1] + q2*gca[2]);
        }
    }
}

// ---- kernel 2: fused FAPE + all pair reductions ----
// grid (24, 24, 2), block (32, 8); each thread handles 4 i-rows for one j.
__global__ __launch_bounds__(256) void fape_kernel(const float* __restrict__ pred,
                                                   const float* __restrict__ gt,
                                                   const int* __restrict__ batch,
                                                   const int* __restrict__ chain,
                                                   float* __restrict__ out) {
    __shared__ float4 sP[TILE * 15];
    __shared__ float4 sG[TILE * 15];
    __shared__ float  sQ[TILE * 12];
    __shared__ int    sBatI[TILE], sBatJ[TILE], sBitI[TILE], sBitJ[TILE], sChI[TILE], sChJ[TILE];
    __shared__ int    sSkip;
    __shared__ float  sred[8][5];

    const int l  = blockIdx.z;
    const int i0 = blockIdx.y * TILE, j0 = blockIdx.x * TILE;
    const int tx = threadIdx.x, ty = threadIdx.y;
    const int tid = ty * 32 + tx;
    float* out_ae = out + OFF_AE;

    // stage j-tile points (448 float4 each, 256 threads -> 2 rounds)
    for (int t = tid; t < TILE * NA; t += 256) {
        int j = t / NA, a = t % NA;
        const float* pp = pred + ((size_t)(l * NR + j0 + j) * NA + a) * 3;
        sP[j * 15 + a] = make_float4(pp[0], pp[1], pp[2], 0.f);
        const float* gp = gt + ((size_t)(j0 + j) * NA + a) * 3;
        sG[j * 15 + a] = make_float4(gp[0], gp[1], gp[2], 0.f);
    }
    for (int t = tid; t < TILE * 12; t += 256)
        sQ[t] = g_Qo[(size_t)(l * NR + i0) * 12 + t];
    if (tid < TILE) {
        sBatI[tid] = batch[i0 + tid]; sBitI[tid] = g_bits[i0 + tid]; sChI[tid] = chain[i0 + tid];
    } else if (tid < 2 * TILE) {
        int t = tid - TILE;
        sBatJ[t] = batch[j0 + t]; sBitJ[t] = g_bits[j0 + t]; sChJ[t] = chain[j0 + t];
    }
    if (tid == 0) {
        // batch is sorted: tile is all cross-batch iff ranges don't overlap
        sSkip = (batch[i0] > batch[j0 + TILE - 1]) || (batch[j0] > batch[i0 + TILE - 1]);
    }
    __syncthreads();

    if (sSkip) {
        if (l == 1) {
#pragma unroll
            for (int r = 0; r < 4; r++)
                out_ae[(size_t)(i0 + ty + 8 * r) * NR + (j0 + tx)] = 0.f;
        }
        return;  // zero contribution to every accumulator
    }

    // Q for my 4 i-rows into registers (LDS broadcasts)
    float q[4][12];
    unsigned mb[4];
    bool sb[4];
#pragma unroll
    for (int r = 0; r < 4; r++) {
        const int row = ty + 8 * r;
#pragma unroll
        for (int k = 0; k < 12; k++) q[r][k] = sQ[row * 12 + k];
        sb[r] = (sBatI[row] == sBatJ[tx]);
        mb[r] = (unsigned)(sBitI[row] & sBitJ[tx]);
    }

    float se[4] = {0.f, 0.f, 0.f, 0.f};
#pragma unroll
    for (int a = 0; a < NA; a++) {
        const float4 g = sG[tx * 15 + a];
        const float4 p = sP[tx * 15 + a];
#pragma unroll
        for (int r = 0; r < 4; r++) {
            float w0 = fmaf(q[r][0], g.x, fmaf(q[r][1], g.y, fmaf(q[r][2], g.z, q[r][9])));
            float w1 = fmaf(q[r][3], g.x, fmaf(q[r][4], g.y, fmaf(q[r][5], g.z, q[r][10])));
            float w2 = fmaf(q[r][6], g.x, fmaf(q[r][7], g.y, fmaf(q[r][8], g.z, q[r][11])));
            float d0 = p.x - w0, d1 = p.y - w1, d2 = p.z - w2;
            float n2 = fmaf(d0, d0, fmaf(d1, d1, d2 * d2));
            float err = sqrt_approx(fmaxf(n2, 1e-6f));
            se[r] += ((mb[r] >> a) & 1u) ? err : 0.f;
        }
    }

    float pIntra = 0.f, pInter = 0.f, pCntS = 0.f, pCntO = 0.f, pDiag = 0.f;
#pragma unroll
    for (int r = 0; r < 4; r++) {
        const int row = ty + 8 * r;
        const int i = i0 + row, j = j0 + tx;
        float fape = sb[r] ? se[r] / fmaxf((float)__popc(mb[r]), 1e-6f) : 0.f;
        if (l == 1) out_ae[(size_t)i * NR + j] = fape;
        if (sb[r] && mb[r] != 0u) {          // pm2
            float clip = fminf(fape, 10.f);
            if (sChI[row] == sChJ[tx]) { pIntra += clip; pCntS += 1.f; }
            else                       { pInter += clip; pCntO += 1.f; }
        }
        if (i == j) {
            pDiag += fape;
            if (l == 1) out[OFF_RE + i] = fape;   // rotamer_error[-1]
        }
    }

    // block reduce 5 values (warp = one ty row)
    float vals[5] = { pIntra, pInter, pCntS, pCntO, pDiag };
#pragma unroll
    for (int k = 0; k < 5; k++) {
        float v = warp_sum(vals[k]);
        if (tx == 0) sred[ty][k] = v;
    }
    __syncthreads();
    if (tid < 5) {
        float v = 0.f;
#pragma unroll
        for (int w = 0; w < 8; w++) v += sred[w][tid];
        if (tid == 0) atomicAdd(&g_acc[0 + l], v);          // intra_l
        else if (tid == 1) atomicAdd(&g_acc[2 + l], v);     // inter_l
        else if (tid == 2) { if (l == 0) atomicAdd(&g_acc[4], v); }  // cnt_same (l-invariant)
        else if (tid == 3) { if (l == 0) atomicAdd(&g_acc[5], v); }  // cnt_other
        else atomicAdd(&g_acc[6 + l], v);                   // diag_l
    }
}

// ---- kernel 3: lDDT + final scalar outputs ----
__global__ __launch_bounds__(256) void lddt_kernel(const float* __restrict__ pred,
                                                   const float* __restrict__ gt,
                                                   float* __restrict__ out) {
    __shared__ float sg[NR][3];
    __shared__ float sp[NR][3];
    __shared__ int   srm[NR];
    for (int j = threadIdx.x; j < NR; j += 256) {
        const float* gp = gt + ((size_t)j * NA + 1) * 3;
        sg[j][0] = gp[0]; sg[j][1] = gp[1]; sg[j][2] = gp[2];
        const float* pp = pred + ((size_t)(1 * NR + j) * NA + 1) * 3;  // pred[-1]
        sp[j][0] = pp[0]; sp[j][1] = pp[1]; sp[j][2] = pp[2];
        srm[j] = (g_bits[j] != 0);
    }
    __syncthreads();

    const int i = blockIdx.x;
    const float gix = sg[i][0], giy = sg[i][1], giz = sg[i][2];
    const float pix = sp[i][0], piy = sp[i][1], piz = sp[i][2];
    float suml = 0.f, cnt = 0.f;
    if (srm[i]) {
        for (int j = threadIdx.x; j < NR; j += 256) {
            if (j == i || !srm[j]) continue;
            float dx = gix - sg[j][0], dy = giy - sg[j][1], dz = giz - sg[j][2];
            float gd = sqrt_approx(fmaxf(dx*dx + dy*dy + dz*dz, 1e-6f));
            if (gd < 15.f) {
                float ex = pix - sp[j][0], ey = piy - sp[j][1], ez = piz - sp[j][2];
                float d = sqrt_approx(fmaxf(ex*ex + ey*ey + ez*ez, 1e-6f));
                float derr = fabsf(gd - d);
                int c = (derr < 0.5f) + (derr < 1.0f) + (derr < 2.0f) + (derr < 4.0f);
                suml += 0.25f * (float)c;
                cnt  += 1.f;
            }
        }
    }
    __shared__ float sred[8][2];
    const int lane = threadIdx.x & 31, wid = threadIdx.x >> 5;
    float v0 = warp_sum(suml), v1 = warp_sum(cnt);
    if (lane == 0) { sred[wid][0] = v0; sred[wid][1] = v1; }
    __syncthreads();
    if (threadIdx.x == 0) {
        float s = 0.f, c = 0.f;
#pragma unroll
        for (int w = 0; w < 8; w++) { s += sred[w][0]; c += sred[w][1]; }
        out[OFF_LDDT + i] = s / fmaxf(c, 1e-6f);
    }

    // block 0, warp 0: finalize the 4 scalar outputs from g_acc
    if (blockIdx.x == 0 && threadIdx.x < 32) {
        float nres = 0.f;
        for (int t = threadIdx.x; t < NR; t += 32)
            nres += (g_bits[t] != 0) ? 1.f : 0.f;
        nres = warp_sum(nres);
        if (threadIdx.x == 0) {
            nres = fmaxf(nres, 1e-6f);
            float invCS = 0.1f / fmaxf(g_acc[4], 1e-6f);
            float invCO = 0.1f / fmaxf(g_acc[5], 1e-6f);
            out[0] = g_acc[0] * invCS + g_acc[2] * invCO;  // fape_loss[0]
            out[1] = g_acc[1] * invCS + g_acc[3] * invCO;  // fape_loss[1]
            out[2] = g_acc[6] / nres;                      // rotamer_loss[0]
            out[3] = g_acc[7] / nres;                      // rotamer_loss[1]
        }
    }
}

extern "C" void kernel_launch(void* const* d_in, const int* in_sizes, int n_in,
                              void* d_out, int out_size) {
    const float* pred  = (const float*)d_in[0];
    const float* gt    = (const float*)d_in[1];
    const float* am    = (const float*)d_in[2];
    const int*   batch = (const int*)d_in[3];
    const int*   chain = (const int*)d_in[4];
    float* out = (float*)d_out;

    frames_kernel<<<(NR + 255) / 256, 256>>>(pred, gt, am);

    dim3 grid(NR / TILE, NR / TILE, LN), blk(32, 8);
    fape_kernel<<<grid, blk>>>(pred, gt, batch, chain, out);

    lddt_kernel<<<NR, 256>>>(pred, gt, out);
}

// round 3
// speedup vs baseline: 2.2643x; 1.2912x over previous
#include <cuda_runtime.h>

#define LN 2
#define NR 768
#define NA 14
#define TILE 32
#define NTILE (NR / TILE)          // 24
#define NFAPE (NTILE * NTILE * LN) // 1152 fape blocks

// output layout: fape_loss[2], rotamer_loss[2], final_ae[768*768], rotamer_error[-1][768], lddt[768]
#define OFF_AE   4
#define OFF_RE   (4 + NR * NR)
#define OFF_LDDT (OFF_RE + NR)

// ---- device scratch (zero-initialized at load; re-zeroed by last block every run) ----
__device__ float    g_acc[9];   // intra0,intra1,inter0,inter1,cnt_s,cnt_o,diag0,diag1,nres
__device__ unsigned g_cnt;      // fape blocks done

__device__ __forceinline__ float sqrt_approx(float x) {
    float r; asm("sqrt.approx.f32 %0, %1;" : "=f"(r) : "f"(x)); return r;
}
__device__ __forceinline__ float rsqrt_approx(float x) {
    float r; asm("rsqrt.approx.f32 %0, %1;" : "=f"(r) : "f"(x)); return r;
}
__device__ __forceinline__ float warp_sum(float v) {
#pragma unroll
    for (int o = 16; o > 0; o >>= 1) v += __shfl_down_sync(0xffffffffu, v, o);
    return v;
}

__device__ __forceinline__ void make_frame(const float n[3], const float ca[3], const float c[3],
                                           float e1[3], float e2[3], float e3[3]) {
    e1[0] = c[0] - ca[0]; e1[1] = c[1] - ca[1]; e1[2] = c[2] - ca[2];
    float s1 = e1[0]*e1[0] + e1[1]*e1[1] + e1[2]*e1[2];
    float i1 = rsqrt_approx(fmaxf(s1, 1e-6f));
    e1[0] *= i1; e1[1] *= i1; e1[2] *= i1;
    float v2[3] = { n[0]-ca[0], n[1]-ca[1], n[2]-ca[2] };
    float dt = e1[0]*v2[0] + e1[1]*v2[1] + e1[2]*v2[2];
    e2[0] = v2[0] - dt*e1[0]; e2[1] = v2[1] - dt*e1[1]; e2[2] = v2[2] - dt*e1[2];
    float s2 = e2[0]*e2[0] + e2[1]*e2[1] + e2[2]*e2[2];
    float i2 = rsqrt_approx(fmaxf(s2, 1e-6f));
    e2[0] *= i2; e2[1] *= i2; e2[2] *= i2;
    e3[0] = e1[1]*e2[2] - e1[2]*e2[1];
    e3[1] = e1[2]*e2[0] - e1[0]*e2[2];
    e3[2] = e1[0]*e2[1] - e1[1]*e2[0];
}

// compute Q = Rp Rg^T (row-major 9) and o = tp - Q tg (3) for one (l, i)
__device__ __forceinline__ void compute_Qo(const float* __restrict__ pred,
                                           const float* __restrict__ gt,
                                           int l, int i, float* dst /*12 floats*/) {
    const float* gb = gt + (size_t)i * NA * 3;
    float gn[3]  = { gb[0], gb[1], gb[2] };
    float gca[3] = { gb[3], gb[4], gb[5] };
    float gc[3]  = { gb[6], gb[7], gb[8] };
    float e1g[3], e2g[3], e3g[3];
    make_frame(gn, gca, gc, e1g, e2g, e3g);

    const float* pb = pred + (size_t)(l * NR + i) * NA * 3;
    float pn[3]  = { pb[0], pb[1], pb[2] };
    float pca[3] = { pb[3], pb[4], pb[5] };
    float pc[3]  = { pb[6], pb[7], pb[8] };
    float e1p[3], e2p[3], e3p[3];
    make_frame(pn, pca, pc, e1p, e2p, e3p);

#pragma unroll
    for (int d = 0; d < 3; d++) {
        float q0 = e1p[d]*e1g[0] + e2p[d]*e2g[0] + e3p[d]*e3g[0];
        float q1 = e1p[d]*e1g[1] + e2p[d]*e2g[1] + e3p[d]*e3g[1];
        float q2 = e1p[d]*e1g[2] + e2p[d]*e2g[2] + e3p[d]*e3g[2];
        dst[3*d+0] = q0; dst[3*d+1] = q1; dst[3*d+2] = q2;
        dst[9 + d] = pca[d] - (q0*gca[0] + q1*gca[1] + q2*gca[2]);
    }
}

__device__ __forceinline__ int atom_bits(const float* __restrict__ am, int i) {
    int bits = 0;
#pragma unroll
    for (int a = 0; a < NA; a++)
        if (am[i * NA + a] > 0.f) bits |= (1 << a);
    return bits;
}

// ---- single fused kernel: grid (24, 24, 3), block (32, 8) ----
// z in {0,1}: fape tiles (frames computed in-block). z==2: lddt rows.
__global__ __launch_bounds__(256) void fused_kernel(const float* __restrict__ pred,
                                                    const float* __restrict__ gt,
                                                    const float* __restrict__ am,
                                                    const int* __restrict__ batch,
                                                    const int* __restrict__ chain,
                                                    float* __restrict__ out) {
    const int tx = threadIdx.x, ty = threadIdx.y;
    const int tid = ty * 32 + tx;

    if (blockIdx.z == 2) {
        // ================= lDDT =================
        __shared__ float sg[NR][3];
        __shared__ float sp[NR][3];
        __shared__ int   srm[NR];
        __shared__ float sred[8][2];
        for (int j = tid; j < NR; j += 256) {
            const float* gp = gt + ((size_t)j * NA + 1) * 3;
            sg[j][0] = gp[0]; sg[j][1] = gp[1]; sg[j][2] = gp[2];
            const float* pp = pred + ((size_t)(1 * NR + j) * NA + 1) * 3;  // pred[-1]
            sp[j][0] = pp[0]; sp[j][1] = pp[1]; sp[j][2] = pp[2];
            srm[j] = (atom_bits(am, j) != 0);
        }
        __syncthreads();

        const int blk = blockIdx.y * NTILE + blockIdx.x;  // 0..575
        for (int i = blk; i < NR; i += NTILE * NTILE) {
            const float gix = sg[i][0], giy = sg[i][1], giz = sg[i][2];
            const float pix = sp[i][0], piy = sp[i][1], piz = sp[i][2];
            float suml = 0.f, cnt = 0.f;
            if (srm[i]) {
                for (int j = tid; j < NR; j += 256) {
                    if (j == i || !srm[j]) continue;
                    float dx = gix - sg[j][0], dy = giy - sg[j][1], dz = giz - sg[j][2];
                    float gd = sqrt_approx(fmaxf(dx*dx + dy*dy + dz*dz, 1e-6f));
                    if (gd < 15.f) {
                        float ex = pix - sp[j][0], ey = piy - sp[j][1], ez = piz - sp[j][2];
                        float d = sqrt_approx(fmaxf(ex*ex + ey*ey + ez*ez, 1e-6f));
                        float derr = fabsf(gd - d);
                        int c = (derr < 0.5f) + (derr < 1.0f) + (derr < 2.0f) + (derr < 4.0f);
                        suml += 0.25f * (float)c;
                        cnt  += 1.f;
                    }
                }
            }
            float v0 = warp_sum(suml), v1 = warp_sum(cnt);
            if (tx == 0) { sred[ty][0] = v0; sred[ty][1] = v1; }
            __syncthreads();
            if (tid == 0) {
                float s = 0.f, c = 0.f;
#pragma unroll
                for (int w = 0; w < 8; w++) { s += sred[w][0]; c += sred[w][1]; }
                out[OFF_LDDT + i] = s / fmaxf(c, 1e-6f);
            }
            __syncthreads();
        }
        return;
    }

    // ================= FAPE tile =================
    __shared__ float4 sP[TILE * 15];
    __shared__ float4 sG[TILE * 15];
    __shared__ float  sQ[TILE * 12];
    __shared__ int    sBatI[TILE], sBatJ[TILE], sBitI[TILE], sBitJ[TILE], sChI[TILE], sChJ[TILE];
    __shared__ float  sred[8][5];

    const int l  = blockIdx.z;
    const int i0 = blockIdx.y * TILE, j0 = blockIdx.x * TILE;
    float* out_ae = out + OFF_AE;

    // warp 0: compute Q/o for my i-tile rows (one row per lane)
    if (tid < TILE) {
        compute_Qo(pred, gt, l, i0 + tid, &sQ[tid * 12]);
        sBatI[tid] = batch[i0 + tid];
        sChI[tid]  = chain[i0 + tid];
        sBitI[tid] = atom_bits(am, i0 + tid);
    } else if (tid < 2 * TILE) {
        int t = tid - TILE;
        sBatJ[t] = batch[j0 + t];
        sChJ[t]  = chain[j0 + t];
        sBitJ[t] = atom_bits(am, j0 + t);
    }
    // remaining warps: stage j-tile point data
    for (int t = tid - 64; t >= 0 && t < TILE * NA; t += 192) {
        int j = t / NA, a = t % NA;
        const float* pp = pred + ((size_t)(l * NR + j0 + j) * NA + a) * 3;
        sP[j * 15 + a] = make_float4(pp[0], pp[1], pp[2], 0.f);
        const float* gp = gt + ((size_t)(j0 + j) * NA + a) * 3;
        sG[j * 15 + a] = make_float4(gp[0], gp[1], gp[2], 0.f);
    }
    __syncthreads();

    // nres contribution: 24 blocks (l==0, j0==0) count residues in their i-tile
    if (l == 0 && blockIdx.x == 0 && tid < TILE) {
        float n = warp_sum((sBitI[tid] != 0) ? 1.f : 0.f);
        if (tid == 0) atomicAdd(&g_acc[8], n);
    }

    // batch sorted: skip tile if i/j batch ranges don't overlap
    const bool skip = (sBatI[0] > sBatJ[TILE - 1]) || (sBatJ[0] > sBatI[TILE - 1]);

    if (!skip) {
        float q[4][12];
        unsigned mb[4];
        bool sb[4];
#pragma unroll
        for (int r = 0; r < 4; r++) {
            const int row = ty + 8 * r;
#pragma unroll
            for (int k = 0; k < 12; k++) q[r][k] = sQ[row * 12 + k];
            sb[r] = (sBatI[row] == sBatJ[tx]);
            mb[r] = (unsigned)(sBitI[row] & sBitJ[tx]);
        }

        float se[4] = {0.f, 0.f, 0.f, 0.f};
#pragma unroll
        for (int a = 0; a < NA; a++) {
            const float4 g = sG[tx * 15 + a];
            const float4 p = sP[tx * 15 + a];
#pragma unroll
            for (int r = 0; r < 4; r++) {
                float w0 = fmaf(q[r][0], g.x, fmaf(q[r][1], g.y, fmaf(q[r][2], g.z, q[r][9])));
                float w1 = fmaf(q[r][3], g.x, fmaf(q[r][4], g.y, fmaf(q[r][5], g.z, q[r][10])));
                float w2 = fmaf(q[r][6], g.x, fmaf(q[r][7], g.y, fmaf(q[r][8], g.z, q[r][11])));
                float d0 = p.x - w0, d1 = p.y - w1, d2 = p.z - w2;
                float n2 = fmaf(d0, d0, fmaf(d1, d1, d2 * d2));
                float err = sqrt_approx(fmaxf(n2, 1e-6f));
                se[r] += ((mb[r] >> a) & 1u) ? err : 0.f;
            }
        }

        float pIntra = 0.f, pInter = 0.f, pCntS = 0.f, pCntO = 0.f, pDiag = 0.f;
#pragma unroll
        for (int r = 0; r < 4; r++) {
            const int row = ty + 8 * r;
            const int i = i0 + row, j = j0 + tx;
            float fape = sb[r] ? se[r] / fmaxf((float)__popc(mb[r]), 1e-6f) : 0.f;
            if (l == 1) out_ae[(size_t)i * NR + j] = fape;
            if (sb[r] && mb[r] != 0u) {
                float clip = fminf(fape, 10.f);
                if (sChI[row] == sChJ[tx]) { pIntra += clip; pCntS += 1.f; }
                else                       { pInter += clip; pCntO += 1.f; }
            }
            if (i == j) {
                pDiag += fape;
                if (l == 1) out[OFF_RE + i] = fape;
            }
        }

        float vals[5] = { pIntra, pInter, pCntS, pCntO, pDiag };
#pragma unroll
        for (int k = 0; k < 5; k++) {
            float v = warp_sum(vals[k]);
            if (tx == 0) sred[ty][k] = v;
        }
        __syncthreads();
        if (tid < 5) {
            float v = 0.f;
#pragma unroll
            for (int w = 0; w < 8; w++) v += sred[w][tid];
            if (tid == 0) atomicAdd(&g_acc[0 + l], v);
            else if (tid == 1) atomicAdd(&g_acc[2 + l], v);
            else if (tid == 2) { if (l == 0) atomicAdd(&g_acc[4], v); }
            else if (tid == 3) { if (l == 0) atomicAdd(&g_acc[5], v); }
            else atomicAdd(&g_acc[6 + l], v);
        }
    } else if (l == 1) {
#pragma unroll
        for (int r = 0; r < 4; r++)
            out_ae[(size_t)(i0 + ty + 8 * r) * NR + (j0 + tx)] = 0.f;
    }

    // done-counter; last fape block finalizes scalars and resets state
    __syncthreads();
    if (tid == 0) {
        __threadfence();
        unsigned done = atomicAdd(&g_cnt, 1u);
        if (done == NFAPE - 1) {
            float nres = fmaxf(g_acc[8], 1e-6f);
            float invCS = 0.1f / fmaxf(g_acc[4], 1e-6f);
            float invCO = 0.1f / fmaxf(g_acc[5], 1e-6f);
            out[0] = g_acc[0] * invCS + g_acc[2] * invCO;  // fape_loss[0]
            out[1] = g_acc[1] * invCS + g_acc[3] * invCO;  // fape_loss[1]
            out[2] = g_acc[6] / nres;                      // rotamer_loss[0]
            out[3] = g_acc[7] / nres;                      // rotamer_loss[1]
#pragma unroll
            for (int k = 0; k < 9; k++) g_acc[k] = 0.f;    // reset for next replay
            __threadfence();
            g_cnt = 0u;
        }
    }
}

extern "C" void kernel_launch(void* const* d_in, const int* in_sizes, int n_in,
                              void* d_out, int out_size) {
    const float* pred  = (const float*)d_in[0];
    const float* gt    = (const float*)d_in[1];
    const float* am    = (const float*)d_in[2];
    const int*   batch = (const int*)d_in[3];
    const int*   chain = (const int*)d_in[4];
    float* out = (float*)d_out;

    dim3 grid(NTILE, NTILE, 3), blk(32, 8);
    fused_kernel<<<grid, blk>>>(pred, gt, am, batch, chain, out);
}